// round 15
// baseline (speedup 1.0000x reference)
#include <cuda_runtime.h>
#include <math_constants.h>
#include <cstdint>

#define NB 2
#define NQ 2048
#define NKK 2048
#define DMODEL 512
#define NH 8
#define DHEAD 64
#define NF 5
#define LOG2E 1.44269504088896f

#define NLUT 2048
#define DMAX 14.143f
#define LUT_H (DMAX / NLUT)
#define LUT_K (NLUT / DMAX)

// Scratch (allocation-free rule: __device__ globals)
__device__ float g_q[NB*NH*NQ*DHEAD];     // tf32-rounded bits
__device__ float g_k[NB*NH*NKK*DHEAD];    // tf32-rounded bits
__device__ float g_v[NB*NH*NKK*DHEAD];    // tf32-rounded bits
__device__ float g_ctx[NB*NQ*DMODEL];     // fp32

__device__ __forceinline__ float ex2f(float x) {
    float y; asm("ex2.approx.ftz.f32 %0, %1;" : "=f"(y) : "f"(x)); return y;
}
__device__ __forceinline__ float rsqrtaf(float x) {
    float y; asm("rsqrt.approx.ftz.f32 %0, %1;" : "=f"(y) : "f"(x)); return y;
}
__device__ __forceinline__ uint32_t f2tf32(float x) {
    uint32_t r; asm("cvt.rna.tf32.f32 %0, %1;" : "=r"(r) : "f"(x)); return r;
}
__device__ __forceinline__ void mma_tf32(float c[4],
    uint32_t a0, uint32_t a1, uint32_t a2, uint32_t a3,
    uint32_t b0, uint32_t b1)
{
    asm volatile(
        "mma.sync.aligned.m16n8k8.row.col.f32.tf32.tf32.f32 "
        "{%0,%1,%2,%3}, {%4,%5,%6,%7}, {%8,%9}, {%0,%1,%2,%3};\n"
        : "+f"(c[0]), "+f"(c[1]), "+f"(c[2]), "+f"(c[3])
        : "r"(a0), "r"(a1), "r"(a2), "r"(a3), "r"(b0), "r"(b1));
}
// ldmatrix x4 of b16 tiles; as tf32: each 8x4 f32 piece, thread l -> (l/4, l%4).
__device__ __forceinline__ void ldsm4(uint32_t r[4], uint32_t addr) {
    asm volatile("ldmatrix.sync.aligned.m8n8.x4.shared.b16 {%0,%1,%2,%3}, [%4];"
        : "=r"(r[0]), "=r"(r[1]), "=r"(r[2]), "=r"(r[3]) : "r"(addr));
}

// ---------------------------------------------------------------------------
// tf32 GEMM: out = (X[M,512] @ W[512,512] + bias) * scale
// CTA 256x64 tile, 256 threads (8 warps), warp = 32 rows x 64 cols.
// A fragments via ldmatrix; B scalar (reused across both m16 halves).
// ---------------------------------------------------------------------------
template<int SPLIT>
__device__ __forceinline__ void gemm_body(
    const float* __restrict__ X, const float* __restrict__ W,
    const float* __restrict__ bias, float* __restrict__ out, float scale)
{
    __shared__ float As[256 * 20];  // [m][k16] pad 20 (80B rows: LDSM conflict-free)
    __shared__ float Bs[16 * 72];   // [k][n64] pad 72

    const int tid  = threadIdx.x;
    const int warp = tid >> 5, lane = tid & 31;
    const int grp  = lane >> 2, qd = lane & 3;
    const int bm = blockIdx.y * 256, bn = blockIdx.x * 64;

    const int piece = lane >> 3, pr = lane & 7;
    const uint32_t as_u32 = (uint32_t)__cvta_generic_to_shared(As);
    // A-frag ldsm base: row = warp*32 + half*16 + (piece&1)*8 + pr, col (piece>>1)*4
    const uint32_t aA = as_u32 +
        ((warp * 32 + ((piece & 1) << 3) + pr) * 20 + ((piece >> 1) << 2)) * 4;

    float C[2][8][4] = {};

    for (int k0 = 0; k0 < 512; k0 += 16) {
        __syncthreads();
        #pragma unroll
        for (int i = tid; i < 1024; i += 256) {          // A: 256x16
            int m = i >> 2, c = i & 3;
            float4 x = *(const float4*)(X + (size_t)(bm + m) * 512 + k0 + c * 4);
            uint4 t = { f2tf32(x.x), f2tf32(x.y), f2tf32(x.z), f2tf32(x.w) };
            *(uint4*)&As[m * 20 + c * 4] = t;
        }
        {                                                // B: 16x64
            int kk = tid >> 4, c = tid & 15;
            float4 w = *(const float4*)(W + (size_t)(k0 + kk) * 512 + bn + c * 4);
            uint4 t = { f2tf32(w.x), f2tf32(w.y), f2tf32(w.z), f2tf32(w.w) };
            *(uint4*)&Bs[kk * 72 + c * 4] = t;
        }
        __syncthreads();

        #pragma unroll
        for (int k8 = 0; k8 < 2; k8++) {
            uint32_t a0[4], a1[4];
            ldsm4(a0, aA + k8 * 32);
            ldsm4(a1, aA + 16 * 80 + k8 * 32);
            #pragma unroll
            for (int j = 0; j < 8; j++) {
                uint32_t bb0 = __float_as_uint(Bs[(k8*8 + qd    ) * 72 + j*8 + grp]);
                uint32_t bb1 = __float_as_uint(Bs[(k8*8 + qd + 4) * 72 + j*8 + grp]);
                mma_tf32(C[0][j], a0[0], a0[1], a0[2], a0[3], bb0, bb1);
                mma_tf32(C[1][j], a1[0], a1[1], a1[2], a1[3], bb0, bb1);
            }
        }
    }

    #pragma unroll
    for (int half = 0; half < 2; half++) {
        const int r0 = bm + warp * 32 + half * 16 + grp;
        #pragma unroll
        for (int j = 0; j < 8; j++) {
            int n = bn + j * 8 + 2 * qd;
            float b0 = bias[n], b1 = bias[n + 1];
            float o00 = (C[half][j][0] + b0) * scale, o01 = (C[half][j][1] + b1) * scale;
            float o10 = (C[half][j][2] + b0) * scale, o11 = (C[half][j][3] + b1) * scale;
            if (SPLIT) {
                float2 o0 = { __uint_as_float(f2tf32(o00)), __uint_as_float(f2tf32(o01)) };
                float2 o1 = { __uint_as_float(f2tf32(o10)), __uint_as_float(f2tf32(o11)) };
                int hh = n >> 6, dh = n & 63;
                int ba = r0 >> 11, s0 = r0 & 2047;
                *(float2*)(out + (((size_t)(ba * NH + hh) * NQ + s0) * 64 + dh)) = o0;
                int r1 = r0 + 8, ba1 = r1 >> 11, s1 = r1 & 2047;
                *(float2*)(out + (((size_t)(ba1 * NH + hh) * NQ + s1) * 64 + dh)) = o1;
            } else {
                float2 o0 = { o00, o01 }, o1 = { o10, o11 };
                *(float2*)(out + (size_t)r0 * 512 + n) = o0;
                *(float2*)(out + (size_t)(r0 + 8) * 512 + n) = o1;
            }
        }
    }
}

__global__ __launch_bounds__(256) void gemm_qkv_kernel(
    const float* __restrict__ qs, const float* __restrict__ ks, const float* __restrict__ vs,
    const float* __restrict__ Wq, const float* __restrict__ Wk, const float* __restrict__ Wv,
    const float* __restrict__ bq, const float* __restrict__ bk, const float* __restrict__ bv,
    float* __restrict__ gq, float* __restrict__ gk, float* __restrict__ gv)
{
    const int z = blockIdx.z;
    const float* X = (z == 0) ? qs : (z == 1) ? ks : vs;
    const float* W = (z == 0) ? Wq : (z == 1) ? Wk : Wv;
    const float* B = (z == 0) ? bq : (z == 1) ? bk : bv;
    float* O = (z == 0) ? gq : (z == 1) ? gk : gv;
    gemm_body<1>(X, W, B, O, (z == 0) ? 0.125f : 1.0f);
}

__global__ __launch_bounds__(256) void gemm_o_kernel(
    const float* __restrict__ X, const float* __restrict__ W,
    const float* __restrict__ bias, float* __restrict__ out)
{
    gemm_body<0>(X, W, bias, out, 1.0f);
}

// ---------------------------------------------------------------------------
// Flash attention: tf32 mma, smem LUT bias, ldmatrix fragment loads.
// Grid (Q/128, H, B), 256 threads (8 warps), warp = 16 q-rows x 64 keys.
// V stored TRANSPOSED in smem (VsT[dh][key]) so PV B-frags come via ldmatrix.
// ---------------------------------------------------------------------------
#define QS_F   (128 * 68)
#define KS_F   (64 * 68)
#define VS_F   (64 * 68)
#define KS_OFFB (QS_F * 4)
#define VS_OFFB ((QS_F + KS_F) * 4)
#define ATTN_SMEM_FLOATS (QS_F + KS_F + VS_F + NLUT*2 + 2*128 + 2*64)
#define ATTN_SMEM_BYTES  (ATTN_SMEM_FLOATS * 4)

__global__ __launch_bounds__(256, 2) void attn_kernel(
    const float* __restrict__ qlocs, const float* __restrict__ klocs,
    const float* __restrict__ pa, const float* __restrict__ pb,
    const float* __restrict__ pc, const int* __restrict__ vlens)
{
    extern __shared__ float smem[];
    float*  Qs   = smem;                      // [128][68] tf32 bits
    float*  Ks   = Qs + QS_F;                 // [64][68]  (key, dh)
    float*  VsT  = Ks + KS_F;                 // [64][68]  (dh, key) TRANSPOSED
    float2* lut  = (float2*)(VsT + VS_F);     // [2048] (value, slope)
    float*  qlx  = (float*)(lut + NLUT);      // [128]
    float*  qly  = qlx + 128;
    float*  klx  = qly + 128;                 // [64]
    float*  kly  = klx + 64;

    const int tid  = threadIdx.x;
    const int warp = tid >> 5, lane = tid & 31;
    const int grp  = lane >> 2, qd = lane & 3;
    const int q0 = blockIdx.x * 128;
    const int h  = blockIdx.y;
    const int b  = blockIdx.z;
    const int vlen = vlens[b];

    // ldmatrix per-thread addresses
    const int piece = lane >> 3, pr = lane & 7;
    const uint32_t smem_u32 = (uint32_t)__cvta_generic_to_shared(smem);
    const int w16 = warp * 16;
    // A from Qs: row = w16 + (piece&1)*8 + pr, col = (piece>>1)*4 (+ k8*8)
    const uint32_t qA = smem_u32 +
        ((w16 + ((piece & 1) << 3) + pr) * 68 + ((piece >> 1) << 2)) * 4;
    // B from Ks: row(key) = (piece>>1)*8 + pr (+ jj*16), col(dh) = (piece&1)*4 (+ k8*8)
    const uint32_t kB = smem_u32 + KS_OFFB +
        ((((piece >> 1) << 3) + pr) * 68 + ((piece & 1) << 2)) * 4;
    // B from VsT: row(dh) = (piece>>1)*8 + pr (+ jj*16), col(key) = (piece&1)*4 (+ k8*8)
    const uint32_t vB = smem_u32 + VS_OFFB +
        ((((piece >> 1) << 3) + pr) * 68 + ((piece & 1) << 2)) * 4;

    // ---- build per-head bias LUT (smem) ----
    float ah[NF], nbf[NF], cf[NF];
    #pragma unroll
    for (int f = 0; f < NF; f++) {
        ah[f]  = pa[h * NF + f];
        nbf[f] = -fabsf(pb[h * NF + f]) * LOG2E;
        cf[f]  = pc[h * NF + f];
    }
    for (int i = tid; i < NLUT; i += 256) {
        float d0 = i * LUT_H, d1 = d0 + LUT_H;
        float v0 = 0.f, v1 = 0.f;
        #pragma unroll
        for (int f = 0; f < NF; f++) {
            float t0 = d0 - cf[f], t1 = d1 - cf[f];
            v0 = fmaf(ah[f], ex2f(nbf[f] * t0 * t0), v0);
            v1 = fmaf(ah[f], ex2f(nbf[f] * t1 * t1), v1);
        }
        lut[i] = make_float2(v0, (v1 - v0) * (1.0f / LUT_H));
    }

    // ---- Q tile (raw bits) + q locs ----
    const float* qbase = g_q + ((size_t)(b * NH + h) * NQ + q0) * 64;
    for (int i = tid; i < 2048; i += 256) {
        int r = i >> 4, c = i & 15;
        *(uint4*)&Qs[r * 68 + c * 4] = *(const uint4*)(qbase + (size_t)r * 64 + c * 4);
    }
    if (tid < 128) {
        float2 ql = *(const float2*)(qlocs + ((size_t)b * NQ + q0 + tid) * 2);
        qlx[tid] = ql.x; qly[tid] = ql.y;
    }
    __syncthreads();

    const int rr = w16 + grp;             // first owned q-row in CTA tile
    const float qx0 = qlx[rr],     qy0 = qly[rr];
    const float qx1 = qlx[rr + 8], qy1 = qly[rr + 8];

    float O[8][4] = {};
    float m0 = -CUDART_INF_F, m1 = -CUDART_INF_F, l0 = 0.f, l1 = 0.f;

    const int ntiles = (vlen + 63) >> 6;
    const float* kptr = g_k + (size_t)(b * NH + h) * NKK * 64;
    const float* vptr = g_v + (size_t)(b * NH + h) * NKK * 64;

    for (int t = 0; t < ntiles; t++) {
        const int kb = t * 64;
        __syncthreads();   // prior PV (reads VsT) done before refill
        // K: natural layout, uint4 copy
        for (int i = tid; i < 1024; i += 256) {
            int key = i >> 4, c = i & 15;
            *(uint4*)&Ks[key * 68 + c * 4] =
                *(const uint4*)(kptr + (size_t)(kb + key) * 64 + c * 4);
        }
        // V: transposed store (key-fast lanes -> conflict-free STS)
        for (int i = tid; i < 1024; i += 256) {
            int key = i & 63, cq = i >> 6;   // cq 0..15
            float4 v = *(const float4*)(vptr + (size_t)(kb + key) * 64 + cq * 4);
            VsT[(cq*4 + 0) * 68 + key] = v.x;
            VsT[(cq*4 + 1) * 68 + key] = v.y;
            VsT[(cq*4 + 2) * 68 + key] = v.z;
            VsT[(cq*4 + 3) * 68 + key] = v.w;
        }
        if (tid < 64) {
            float2 kl = *(const float2*)(klocs + ((size_t)b * NKK + kb + tid) * 2);
            klx[tid] = kl.x; kly[tid] = kl.y;
        }
        __syncthreads();

        // ---- scores: S = Q @ K^T via tf32 mma + ldmatrix ----
        float S[8][4] = {};
        #pragma unroll
        for (int k8 = 0; k8 < 8; k8++) {
            uint32_t a[4]; ldsm4(a, qA + k8 * 32);
            #pragma unroll
            for (int jj = 0; jj < 4; jj++) {
                uint32_t bf[4]; ldsm4(bf, kB + jj * (16*68*4) + k8 * 32);
                mma_tf32(S[2*jj],     a[0], a[1], a[2], a[3], bf[0], bf[1]);
                mma_tf32(S[2*jj + 1], a[0], a[1], a[2], a[3], bf[2], bf[3]);
            }
        }

        // ---- bias (smem LUT) + mask ----
        const bool partial = (kb + 64 > vlen);
        #pragma unroll
        for (int j = 0; j < 8; j++) {
            int cl = j * 8 + 2 * qd;
            #pragma unroll
            for (int e = 0; e < 2; e++) {
                float kx = klx[cl + e], ky = kly[cl + e];
                // row rr
                float dx = qx0 - kx, dy = qy0 - ky;
                float d2 = fmaxf(fmaf(dx, dx, dy * dy), 1e-24f);
                float d = d2 * rsqrtaf(d2);
                int ii = min((int)(d * LUT_K), NLUT - 1);
                float2 vs = lut[ii];
                S[j][e] += fmaf(vs.y, d - ii * LUT_H, vs.x);
                // row rr+8
                dx = qx1 - kx; dy = qy1 - ky;
                d2 = fmaxf(fmaf(dx, dx, dy * dy), 1e-24f);
                d = d2 * rsqrtaf(d2);
                ii = min((int)(d * LUT_K), NLUT - 1);
                vs = lut[ii];
                S[j][2 + e] += fmaf(vs.y, d - ii * LUT_H, vs.x);
            }
            if (partial) {
                if (kb + cl     >= vlen) { S[j][0] = -CUDART_INF_F; S[j][2] = -CUDART_INF_F; }
                if (kb + cl + 1 >= vlen) { S[j][1] = -CUDART_INF_F; S[j][3] = -CUDART_INF_F; }
            }
        }

        // ---- online softmax (rows rr, rr+8; quad lanes share rows) ----
        float tm0 = -CUDART_INF_F, tm1 = -CUDART_INF_F;
        #pragma unroll
        for (int j = 0; j < 8; j++) {
            tm0 = fmaxf(tm0, fmaxf(S[j][0], S[j][1]));
            tm1 = fmaxf(tm1, fmaxf(S[j][2], S[j][3]));
        }
        tm0 = fmaxf(tm0, __shfl_xor_sync(0xffffffffu, tm0, 1));
        tm0 = fmaxf(tm0, __shfl_xor_sync(0xffffffffu, tm0, 2));
        tm1 = fmaxf(tm1, __shfl_xor_sync(0xffffffffu, tm1, 1));
        tm1 = fmaxf(tm1, __shfl_xor_sync(0xffffffffu, tm1, 2));
        float mn0 = fmaxf(m0, tm0), mn1 = fmaxf(m1, tm1);
        float sc0 = ex2f((m0 - mn0) * LOG2E);
        float sc1 = ex2f((m1 - mn1) * LOG2E);
        m0 = mn0; m1 = mn1;

        // exp + C->A fragment relayout via intra-quad shuffles
        float rs0 = 0.f, rs1 = 0.f;
        const int s1 = qd >> 1, s2 = s1 + 2;
        const bool odd = (qd & 1);
        #pragma unroll
        for (int j = 0; j < 8; j++) {
            float p0 = ex2f((S[j][0] - mn0) * LOG2E);
            float p1 = ex2f((S[j][1] - mn0) * LOG2E);
            float p2 = ex2f((S[j][2] - mn1) * LOG2E);
            float p3 = ex2f((S[j][3] - mn1) * LOG2E);
            rs0 += p0 + p1;
            rs1 += p2 + p3;
            float u0 = __shfl_sync(0xffffffffu, p0, s1, 4);
            float u1 = __shfl_sync(0xffffffffu, p1, s1, 4);
            float w0 = __shfl_sync(0xffffffffu, p0, s2, 4);
            float w1 = __shfl_sync(0xffffffffu, p1, s2, 4);
            float t0 = __shfl_sync(0xffffffffu, p2, s1, 4);
            float t1 = __shfl_sync(0xffffffffu, p3, s1, 4);
            float v0 = __shfl_sync(0xffffffffu, p2, s2, 4);
            float v1 = __shfl_sync(0xffffffffu, p3, s2, 4);
            S[j][0] = __uint_as_float(f2tf32(odd ? u1 : u0));
            S[j][1] = __uint_as_float(f2tf32(odd ? t1 : t0));
            S[j][2] = __uint_as_float(f2tf32(odd ? w1 : w0));
            S[j][3] = __uint_as_float(f2tf32(odd ? v1 : v0));
        }
        rs0 += __shfl_xor_sync(0xffffffffu, rs0, 1);
        rs0 += __shfl_xor_sync(0xffffffffu, rs0, 2);
        rs1 += __shfl_xor_sync(0xffffffffu, rs1, 1);
        rs1 += __shfl_xor_sync(0xffffffffu, rs1, 2);
        l0 = l0 * sc0 + rs0;
        l1 = l1 * sc1 + rs1;
        #pragma unroll
        for (int j = 0; j < 8; j++) {
            O[j][0] *= sc0; O[j][1] *= sc0;
            O[j][2] *= sc1; O[j][3] *= sc1;
        }

        // ---- PV: O += P @ V via tf32 mma (V B-frags via ldmatrix of VsT) ----
        #pragma unroll
        for (int k8 = 0; k8 < 8; k8++) {
            uint32_t a0 = __float_as_uint(S[k8][0]);
            uint32_t a1 = __float_as_uint(S[k8][1]);
            uint32_t a2 = __float_as_uint(S[k8][2]);
            uint32_t a3 = __float_as_uint(S[k8][3]);
            #pragma unroll
            for (int jj = 0; jj < 4; jj++) {
                uint32_t vf[4]; ldsm4(vf, vB + jj * (16*68*4) + k8 * 32);
                mma_tf32(O[2*jj],     a0, a1, a2, a3, vf[0], vf[1]);
                mma_tf32(O[2*jj + 1], a0, a1, a2, a3, vf[2], vf[3]);
            }
        }
    }

    // ---- normalize + write context ----
    float li0 = 1.0f / l0, li1 = 1.0f / l1;
    float* obase = g_ctx + ((size_t)(b * NQ + q0 + rr)) * 512 + h * 64;
    #pragma unroll
    for (int j = 0; j < 8; j++) {
        int cl = j * 8 + 2 * qd;
        float2 o0 = { O[j][0] * li0, O[j][1] * li0 };
        float2 o1 = { O[j][2] * li1, O[j][3] * li1 };
        *(float2*)(obase + cl) = o0;
        *(float2*)(obase + (size_t)8 * 512 + cl) = o1;
    }
}

// ---------------------------------------------------------------------------
extern "C" void kernel_launch(void* const* d_in, const int* in_sizes, int n_in,
                              void* d_out, int out_size)
{
    const float* qs    = (const float*)d_in[0];
    const float* ks    = (const float*)d_in[1];
    const float* vs    = (const float*)d_in[2];
    const float* qlocs = (const float*)d_in[3];
    const float* klocs = (const float*)d_in[4];
    const float* Wq    = (const float*)d_in[5];
    const float* bq    = (const float*)d_in[6];
    const float* Wk    = (const float*)d_in[7];
    const float* bk    = (const float*)d_in[8];
    const float* Wv    = (const float*)d_in[9];
    const float* bv    = (const float*)d_in[10];
    const float* Wo    = (const float*)d_in[11];
    const float* bo    = (const float*)d_in[12];
    const float* pa    = (const float*)d_in[13];
    const float* pb    = (const float*)d_in[14];
    const float* pc    = (const float*)d_in[15];
    const int*   vlens = (const int*)d_in[16];
    float* out = (float*)d_out;

    float *gq, *gk, *gv, *gctx;
    cudaGetSymbolAddress((void**)&gq,   g_q);
    cudaGetSymbolAddress((void**)&gk,   g_k);
    cudaGetSymbolAddress((void**)&gv,   g_v);
    cudaGetSymbolAddress((void**)&gctx, g_ctx);

    cudaFuncSetAttribute(attn_kernel,
                         cudaFuncAttributeMaxDynamicSharedMemorySize,
                         ATTN_SMEM_BYTES);

    gemm_qkv_kernel<<<dim3(8, 16, 3), 256>>>(qs, ks, vs, Wq, Wk, Wv,
                                             bq, bk, bv, gq, gk, gv);

    attn_kernel<<<dim3(NQ / 128, NH, NB), 256, ATTN_SMEM_BYTES>>>(
        qlocs, klocs, pa, pb, pc, vlens);

    gemm_o_kernel<<<dim3(8, 16), 256>>>(gctx, Wo, bo, out);
}

// round 16
// speedup vs baseline: 1.2664x; 1.2664x over previous
#include <cuda_runtime.h>
#include <math_constants.h>
#include <cstdint>

#define NB 2
#define NQ 2048
#define NKK 2048
#define DMODEL 512
#define NH 8
#define DHEAD 64
#define NF 5
#define LOG2E 1.44269504088896f

#define NLUT 2048
#define DMAX 14.143f
#define LUT_H (DMAX / NLUT)
#define LUT_K (NLUT / DMAX)

// Scratch (allocation-free rule: __device__ globals)
__device__ float g_q[NB*NH*NQ*DHEAD];     // tf32-rounded bits
__device__ float g_k[NB*NH*NKK*DHEAD];    // tf32-rounded bits
__device__ float g_v[NB*NH*NKK*DHEAD];    // tf32-rounded bits
__device__ float g_ctx[NB*NQ*DMODEL];     // fp32

__device__ __forceinline__ float ex2f(float x) {
    float y; asm("ex2.approx.ftz.f32 %0, %1;" : "=f"(y) : "f"(x)); return y;
}
__device__ __forceinline__ float rsqrtaf(float x) {
    float y; asm("rsqrt.approx.ftz.f32 %0, %1;" : "=f"(y) : "f"(x)); return y;
}
__device__ __forceinline__ uint32_t f2tf32(float x) {
    uint32_t r; asm("cvt.rna.tf32.f32 %0, %1;" : "=r"(r) : "f"(x)); return r;
}
__device__ __forceinline__ void mma_tf32(float c[4],
    uint32_t a0, uint32_t a1, uint32_t a2, uint32_t a3,
    uint32_t b0, uint32_t b1)
{
    asm volatile(
        "mma.sync.aligned.m16n8k8.row.col.f32.tf32.tf32.f32 "
        "{%0,%1,%2,%3}, {%4,%5,%6,%7}, {%8,%9}, {%0,%1,%2,%3};\n"
        : "+f"(c[0]), "+f"(c[1]), "+f"(c[2]), "+f"(c[3])
        : "r"(a0), "r"(a1), "r"(a2), "r"(a3), "r"(b0), "r"(b1));
}

// ---------------------------------------------------------------------------
// tf32 GEMM: out = (X[M,512] @ W[512,512] + bias) * scale
// CTA 128x64 tile, 256 threads (8 warps), warp = 16 rows x 64 cols.
// K-tile = 32 (half the syncs of R14; same fragment math, same accumulators).
// SPLIT: head-split layout + tf32-rounded store (so attn copies raw bits).
// ---------------------------------------------------------------------------
template<int SPLIT>
__device__ __forceinline__ void gemm_body(
    const float* __restrict__ X, const float* __restrict__ W,
    const float* __restrict__ bias, float* __restrict__ out, float scale)
{
    __shared__ float As[128 * 36];  // [m][k32] pad 36 (conflict-free quads)
    __shared__ float Bs[32 * 72];   // [k][n64] pad 72

    const int tid  = threadIdx.x;
    const int warp = tid >> 5, lane = tid & 31;
    const int grp  = lane >> 2, qd = lane & 3;
    const int bm = blockIdx.y * 128, bn = blockIdx.x * 64;

    float C[8][4] = {};

    for (int k0 = 0; k0 < 512; k0 += 32) {
        __syncthreads();
        #pragma unroll
        for (int i = tid; i < 1024; i += 256) {          // A: 128x32
            int m = i >> 3, c = i & 7;
            float4 x = *(const float4*)(X + (size_t)(bm + m) * 512 + k0 + c * 4);
            uint4 t = { f2tf32(x.x), f2tf32(x.y), f2tf32(x.z), f2tf32(x.w) };
            *(uint4*)&As[m * 36 + c * 4] = t;
        }
        #pragma unroll
        for (int i = tid; i < 512; i += 256) {           // B: 32x64
            int kk = i >> 4, c = i & 15;
            float4 w = *(const float4*)(W + (size_t)(k0 + kk) * 512 + bn + c * 4);
            uint4 t = { f2tf32(w.x), f2tf32(w.y), f2tf32(w.z), f2tf32(w.w) };
            *(uint4*)&Bs[kk * 72 + c * 4] = t;
        }
        __syncthreads();

        #pragma unroll
        for (int k8 = 0; k8 < 4; k8++) {
            int kc = k8 * 8 + qd;
            uint32_t a0 = __float_as_uint(As[(warp*16 + grp    ) * 36 + kc    ]);
            uint32_t a1 = __float_as_uint(As[(warp*16 + grp + 8) * 36 + kc    ]);
            uint32_t a2 = __float_as_uint(As[(warp*16 + grp    ) * 36 + kc + 4]);
            uint32_t a3 = __float_as_uint(As[(warp*16 + grp + 8) * 36 + kc + 4]);
            #pragma unroll
            for (int j = 0; j < 8; j++) {
                uint32_t b0 = __float_as_uint(Bs[(k8*8 + qd    ) * 72 + j*8 + grp]);
                uint32_t b1 = __float_as_uint(Bs[(k8*8 + qd + 4) * 72 + j*8 + grp]);
                mma_tf32(C[j], a0, a1, a2, a3, b0, b1);
            }
        }
    }

    const int r0 = bm + warp * 16 + grp;
    #pragma unroll
    for (int j = 0; j < 8; j++) {
        int n = bn + j * 8 + 2 * qd;
        float b0 = bias[n], b1 = bias[n + 1];
        float o00 = (C[j][0] + b0) * scale, o01 = (C[j][1] + b1) * scale;
        float o10 = (C[j][2] + b0) * scale, o11 = (C[j][3] + b1) * scale;
        if (SPLIT) {
            // tf32-round at store: attention copies raw bits, no cvt in fills
            float2 o0 = { __uint_as_float(f2tf32(o00)), __uint_as_float(f2tf32(o01)) };
            float2 o1 = { __uint_as_float(f2tf32(o10)), __uint_as_float(f2tf32(o11)) };
            int hh = n >> 6, dh = n & 63;
            int ba = r0 >> 11, s0 = r0 & 2047;
            *(float2*)(out + (((size_t)(ba * NH + hh) * NQ + s0) * 64 + dh)) = o0;
            int r1 = r0 + 8, ba1 = r1 >> 11, s1 = r1 & 2047;
            *(float2*)(out + (((size_t)(ba1 * NH + hh) * NQ + s1) * 64 + dh)) = o1;
        } else {
            float2 o0 = { o00, o01 }, o1 = { o10, o11 };
            *(float2*)(out + (size_t)r0 * 512 + n) = o0;
            *(float2*)(out + (size_t)(r0 + 8) * 512 + n) = o1;
        }
    }
}

__global__ __launch_bounds__(256) void gemm_qkv_kernel(
    const float* __restrict__ qs, const float* __restrict__ ks, const float* __restrict__ vs,
    const float* __restrict__ Wq, const float* __restrict__ Wk, const float* __restrict__ Wv,
    const float* __restrict__ bq, const float* __restrict__ bk, const float* __restrict__ bv,
    float* __restrict__ gq, float* __restrict__ gk, float* __restrict__ gv)
{
    const int z = blockIdx.z;
    const float* X = (z == 0) ? qs : (z == 1) ? ks : vs;
    const float* W = (z == 0) ? Wq : (z == 1) ? Wk : Wv;
    const float* B = (z == 0) ? bq : (z == 1) ? bk : bv;
    float* O = (z == 0) ? gq : (z == 1) ? gk : gv;
    gemm_body<1>(X, W, B, O, (z == 0) ? 0.125f : 1.0f);
}

__global__ __launch_bounds__(256) void gemm_o_kernel(
    const float* __restrict__ X, const float* __restrict__ W,
    const float* __restrict__ bias, float* __restrict__ out)
{
    gemm_body<0>(X, W, bias, out, 1.0f);
}

// ---------------------------------------------------------------------------
// Flash attention (R14-identical): tf32 mma + smem LUT bias.
// Grid (Q/128, H, B), 256 threads (8 warps), warp = 16 q-rows x 64 keys.
// Fills are raw uint4 copies (inputs pre-rounded to tf32 by the GEMM).
// ---------------------------------------------------------------------------
#define ATTN_SMEM_FLOATS (128*68 + 64*68 + 64*72 + NLUT*2 + 2*128 + 2*64)
#define ATTN_SMEM_BYTES  (ATTN_SMEM_FLOATS * 4)

__global__ __launch_bounds__(256, 2) void attn_kernel(
    const float* __restrict__ qlocs, const float* __restrict__ klocs,
    const float* __restrict__ pa, const float* __restrict__ pb,
    const float* __restrict__ pc, const int* __restrict__ vlens)
{
    extern __shared__ float smem[];
    float*  Qs   = smem;                      // [128][68] tf32 bits
    float*  Ks   = Qs + 128 * 68;             // [64][68]
    float*  Vs   = Ks + 64 * 68;              // [64][72]
    float2* lut  = (float2*)(Vs + 64 * 72);   // [2048] (value, slope)
    float*  qlx  = (float*)(lut + NLUT);      // [128]
    float*  qly  = qlx + 128;
    float*  klx  = qly + 128;                 // [64]
    float*  kly  = klx + 64;

    const int tid  = threadIdx.x;
    const int warp = tid >> 5, lane = tid & 31;
    const int grp  = lane >> 2, qd = lane & 3;
    const int q0 = blockIdx.x * 128;
    const int h  = blockIdx.y;
    const int b  = blockIdx.z;
    const int vlen = vlens[b];

    // ---- build per-head bias LUT (smem) ----
    float ah[NF], nbf[NF], cf[NF];
    #pragma unroll
    for (int f = 0; f < NF; f++) {
        ah[f]  = pa[h * NF + f];
        nbf[f] = -fabsf(pb[h * NF + f]) * LOG2E;
        cf[f]  = pc[h * NF + f];
    }
    for (int i = tid; i < NLUT; i += 256) {
        float d0 = i * LUT_H, d1 = d0 + LUT_H;
        float v0 = 0.f, v1 = 0.f;
        #pragma unroll
        for (int f = 0; f < NF; f++) {
            float t0 = d0 - cf[f], t1 = d1 - cf[f];
            v0 = fmaf(ah[f], ex2f(nbf[f] * t0 * t0), v0);
            v1 = fmaf(ah[f], ex2f(nbf[f] * t1 * t1), v1);
        }
        lut[i] = make_float2(v0, (v1 - v0) * (1.0f / LUT_H));
    }

    // ---- Q tile (raw bits) + q locs ----
    const float* qbase = g_q + ((size_t)(b * NH + h) * NQ + q0) * 64;
    for (int i = tid; i < 2048; i += 256) {
        int r = i >> 4, c = i & 15;
        *(uint4*)&Qs[r * 68 + c * 4] = *(const uint4*)(qbase + (size_t)r * 64 + c * 4);
    }
    if (tid < 128) {
        float2 ql = *(const float2*)(qlocs + ((size_t)b * NQ + q0 + tid) * 2);
        qlx[tid] = ql.x; qly[tid] = ql.y;
    }
    __syncthreads();

    const int rr = warp * 16 + grp;       // first owned q-row in CTA tile
    const float qx0 = qlx[rr],     qy0 = qly[rr];
    const float qx1 = qlx[rr + 8], qy1 = qly[rr + 8];

    float O[8][4] = {};
    float m0 = -CUDART_INF_F, m1 = -CUDART_INF_F, l0 = 0.f, l1 = 0.f;

    const int ntiles = (vlen + 63) >> 6;
    const float* kptr = g_k + (size_t)(b * NH + h) * NKK * 64;
    const float* vptr = g_v + (size_t)(b * NH + h) * NKK * 64;

    for (int t = 0; t < ntiles; t++) {
        const int kb = t * 64;
        __syncthreads();   // prior PV (reads Vs) done before refill
        for (int i = tid; i < 1024; i += 256) {
            int key = i >> 4, c = i & 15;
            *(uint4*)&Ks[key * 68 + c * 4] =
                *(const uint4*)(kptr + (size_t)(kb + key) * 64 + c * 4);
            *(uint4*)&Vs[key * 72 + c * 4] =
                *(const uint4*)(vptr + (size_t)(kb + key) * 64 + c * 4);
        }
        if (tid < 64) {
            float2 kl = *(const float2*)(klocs + ((size_t)b * NKK + kb + tid) * 2);
            klx[tid] = kl.x; kly[tid] = kl.y;
        }
        __syncthreads();

        // ---- scores: S = Q @ K^T via tf32 mma ----
        float S[8][4] = {};
        #pragma unroll
        for (int k8 = 0; k8 < 8; k8++) {
            int kc = k8 * 8 + qd;
            uint32_t a0 = __float_as_uint(Qs[(rr    ) * 68 + kc    ]);
            uint32_t a1 = __float_as_uint(Qs[(rr + 8) * 68 + kc    ]);
            uint32_t a2 = __float_as_uint(Qs[(rr    ) * 68 + kc + 4]);
            uint32_t a3 = __float_as_uint(Qs[(rr + 8) * 68 + kc + 4]);
            #pragma unroll
            for (int j = 0; j < 8; j++) {
                uint32_t b0 = __float_as_uint(Ks[(j*8 + grp) * 68 + kc    ]);
                uint32_t b1 = __float_as_uint(Ks[(j*8 + grp) * 68 + kc + 4]);
                mma_tf32(S[j], a0, a1, a2, a3, b0, b1);
            }
        }

        // ---- bias (smem LUT) + mask ----
        const bool partial = (kb + 64 > vlen);
        #pragma unroll
        for (int j = 0; j < 8; j++) {
            int cl = j * 8 + 2 * qd;
            #pragma unroll
            for (int e = 0; e < 2; e++) {
                float kx = klx[cl + e], ky = kly[cl + e];
                // row rr
                float dx = qx0 - kx, dy = qy0 - ky;
                float d2 = fmaxf(fmaf(dx, dx, dy * dy), 1e-24f);
                float d = d2 * rsqrtaf(d2);
                int ii = min((int)(d * LUT_K), NLUT - 1);
                float2 vs = lut[ii];
                S[j][e] += fmaf(vs.y, d - ii * LUT_H, vs.x);
                // row rr+8
                dx = qx1 - kx; dy = qy1 - ky;
                d2 = fmaxf(fmaf(dx, dx, dy * dy), 1e-24f);
                d = d2 * rsqrtaf(d2);
                ii = min((int)(d * LUT_K), NLUT - 1);
                vs = lut[ii];
                S[j][2 + e] += fmaf(vs.y, d - ii * LUT_H, vs.x);
            }
            if (partial) {
                if (kb + cl     >= vlen) { S[j][0] = -CUDART_INF_F; S[j][2] = -CUDART_INF_F; }
                if (kb + cl + 1 >= vlen) { S[j][1] = -CUDART_INF_F; S[j][3] = -CUDART_INF_F; }
            }
        }

        // ---- online softmax (rows rr, rr+8; quad lanes share rows) ----
        float tm0 = -CUDART_INF_F, tm1 = -CUDART_INF_F;
        #pragma unroll
        for (int j = 0; j < 8; j++) {
            tm0 = fmaxf(tm0, fmaxf(S[j][0], S[j][1]));
            tm1 = fmaxf(tm1, fmaxf(S[j][2], S[j][3]));
        }
        tm0 = fmaxf(tm0, __shfl_xor_sync(0xffffffffu, tm0, 1));
        tm0 = fmaxf(tm0, __shfl_xor_sync(0xffffffffu, tm0, 2));
        tm1 = fmaxf(tm1, __shfl_xor_sync(0xffffffffu, tm1, 1));
        tm1 = fmaxf(tm1, __shfl_xor_sync(0xffffffffu, tm1, 2));
        float mn0 = fmaxf(m0, tm0), mn1 = fmaxf(m1, tm1);
        float sc0 = ex2f((m0 - mn0) * LOG2E);
        float sc1 = ex2f((m1 - mn1) * LOG2E);
        m0 = mn0; m1 = mn1;

        // exp + C->A fragment relayout via intra-quad shuffles
        float rs0 = 0.f, rs1 = 0.f;
        const int s1 = qd >> 1, s2 = s1 + 2;
        const bool odd = (qd & 1);
        #pragma unroll
        for (int j = 0; j < 8; j++) {
            float p0 = ex2f((S[j][0] - mn0) * LOG2E);
            float p1 = ex2f((S[j][1] - mn0) * LOG2E);
            float p2 = ex2f((S[j][2] - mn1) * LOG2E);
            float p3 = ex2f((S[j][3] - mn1) * LOG2E);
            rs0 += p0 + p1;
            rs1 += p2 + p3;
            float u0 = __shfl_sync(0xffffffffu, p0, s1, 4);
            float u1 = __shfl_sync(0xffffffffu, p1, s1, 4);
            float w0 = __shfl_sync(0xffffffffu, p0, s2, 4);
            float w1 = __shfl_sync(0xffffffffu, p1, s2, 4);
            float t0 = __shfl_sync(0xffffffffu, p2, s1, 4);
            float t1 = __shfl_sync(0xffffffffu, p3, s1, 4);
            float v0 = __shfl_sync(0xffffffffu, p2, s2, 4);
            float v1 = __shfl_sync(0xffffffffu, p3, s2, 4);
            S[j][0] = __uint_as_float(f2tf32(odd ? u1 : u0));
            S[j][1] = __uint_as_float(f2tf32(odd ? t1 : t0));
            S[j][2] = __uint_as_float(f2tf32(odd ? w1 : w0));
            S[j][3] = __uint_as_float(f2tf32(odd ? v1 : v0));
        }
        rs0 += __shfl_xor_sync(0xffffffffu, rs0, 1);
        rs0 += __shfl_xor_sync(0xffffffffu, rs0, 2);
        rs1 += __shfl_xor_sync(0xffffffffu, rs1, 1);
        rs1 += __shfl_xor_sync(0xffffffffu, rs1, 2);
        l0 = l0 * sc0 + rs0;
        l1 = l1 * sc1 + rs1;
        #pragma unroll
        for (int j = 0; j < 8; j++) {
            O[j][0] *= sc0; O[j][1] *= sc0;
            O[j][2] *= sc1; O[j][3] *= sc1;
        }

        // ---- PV: O += P @ V via tf32 mma (A fragments in registers) ----
        #pragma unroll
        for (int k8 = 0; k8 < 8; k8++) {
            uint32_t a0 = __float_as_uint(S[k8][0]);
            uint32_t a1 = __float_as_uint(S[k8][1]);
            uint32_t a2 = __float_as_uint(S[k8][2]);
            uint32_t a3 = __float_as_uint(S[k8][3]);
            #pragma unroll
            for (int j = 0; j < 8; j++) {
                uint32_t b0 = __float_as_uint(Vs[(k8*8 + qd    ) * 72 + j*8 + grp]);
                uint32_t b1 = __float_as_uint(Vs[(k8*8 + qd + 4) * 72 + j*8 + grp]);
                mma_tf32(O[j], a0, a1, a2, a3, b0, b1);
            }
        }
    }

    // ---- normalize + write context ----
    float li0 = 1.0f / l0, li1 = 1.0f / l1;
    float* obase = g_ctx + ((size_t)(b * NQ + q0 + rr)) * 512 + h * 64;
    #pragma unroll
    for (int j = 0; j < 8; j++) {
        int cl = j * 8 + 2 * qd;
        float2 o0 = { O[j][0] * li0, O[j][1] * li0 };
        float2 o1 = { O[j][2] * li1, O[j][3] * li1 };
        *(float2*)(obase + cl) = o0;
        *(float2*)(obase + (size_t)8 * 512 + cl) = o1;
    }
}

// ---------------------------------------------------------------------------
extern "C" void kernel_launch(void* const* d_in, const int* in_sizes, int n_in,
                              void* d_out, int out_size)
{
    const float* qs    = (const float*)d_in[0];
    const float* ks    = (const float*)d_in[1];
    const float* vs    = (const float*)d_in[2];
    const float* qlocs = (const float*)d_in[3];
    const float* klocs = (const float*)d_in[4];
    const float* Wq    = (const float*)d_in[5];
    const float* bq    = (const float*)d_in[6];
    const float* Wk    = (const float*)d_in[7];
    const float* bk    = (const float*)d_in[8];
    const float* Wv    = (const float*)d_in[9];
    const float* bv    = (const float*)d_in[10];
    const float* Wo    = (const float*)d_in[11];
    const float* bo    = (const float*)d_in[12];
    const float* pa    = (const float*)d_in[13];
    const float* pb    = (const float*)d_in[14];
    const float* pc    = (const float*)d_in[15];
    const int*   vlens = (const int*)d_in[16];
    float* out = (float*)d_out;

    float *gq, *gk, *gv, *gctx;
    cudaGetSymbolAddress((void**)&gq,   g_q);
    cudaGetSymbolAddress((void**)&gk,   g_k);
    cudaGetSymbolAddress((void**)&gv,   g_v);
    cudaGetSymbolAddress((void**)&gctx, g_ctx);

    cudaFuncSetAttribute(attn_kernel,
                         cudaFuncAttributeMaxDynamicSharedMemorySize,
                         ATTN_SMEM_BYTES);

    gemm_qkv_kernel<<<dim3(8, 32, 3), 256>>>(qs, ks, vs, Wq, Wk, Wv,
                                             bq, bk, bv, gq, gk, gv);

    attn_kernel<<<dim3(NQ / 128, NH, NB), 256, ATTN_SMEM_BYTES>>>(
        qlocs, klocs, pa, pb, pc, vlens);

    gemm_o_kernel<<<dim3(8, 32), 256>>>(gctx, Wo, bo, out);
}